// round 1
// baseline (speedup 1.0000x reference)
#include <cuda_runtime.h>
#include <math.h>

#define N_POINTS 16384
#define N_PAIRS  65536

// Scratch (no cudaMalloc allowed)
__device__ float2 g_x[N_POINTS];
__device__ double g_part;
__device__ double g_kld;
__device__ double g_pairloss;
__device__ double g_pijsum;

__device__ __forceinline__ float rcp_fast(float x) {
    float r;
    asm("rcp.approx.f32 %0, %1;" : "=f"(r) : "f"(x));
    return r;
}

// -------- kernel 0: zero accumulators (graph-capturable, deterministic) -----
__global__ void k_zero() {
    g_part = 0.0; g_kld = 0.0; g_pairloss = 0.0; g_pijsum = 0.0;
}

// -------- block reduction helper --------------------------------------------
__device__ __forceinline__ float block_reduce(float v, float* smem) {
    #pragma unroll
    for (int o = 16; o > 0; o >>= 1) v += __shfl_xor_sync(0xffffffffu, v, o);
    int lane = threadIdx.x & 31, wid = threadIdx.x >> 5;
    if (lane == 0) smem[wid] = v;
    __syncthreads();
    int nw = blockDim.x >> 5;
    v = (threadIdx.x < nw) ? smem[threadIdx.x] : 0.0f;
    if (wid == 0) {
        #pragma unroll
        for (int o = 16; o > 0; o >>= 1) v += __shfl_xor_sync(0xffffffffu, v, o);
    }
    return v;  // valid in thread 0
}

// -------- kernel 1: x = eps*exp(0.5*lv)+mu, and KLD reduction ---------------
__global__ void k_reparam(const float* __restrict__ mu,
                          const float* __restrict__ lv,
                          const float* __restrict__ eps) {
    __shared__ float sred[32];
    int idx = blockIdx.x * blockDim.x + threadIdx.x;
    float kld = 0.0f;
    if (idx < N_POINTS) {
        float2 m = ((const float2*)mu)[idx];
        float2 l = ((const float2*)lv)[idx];
        float2 e = ((const float2*)eps)[idx];
        float elx = expf(l.x), ely = expf(l.y);
        float2 x;
        x.x = fmaf(e.x, expf(0.5f * l.x), m.x);
        x.y = fmaf(e.y, expf(0.5f * l.y), m.y);
        g_x[idx] = x;
        kld  = (1.0f + l.x - m.x * m.x - elx);
        kld += (1.0f + l.y - m.y * m.y - ely);
    }
    float s = block_reduce(kld, sred);
    if (threadIdx.x == 0) atomicAdd(&g_kld, -0.5 * (double)s);
}

// -------- kernel 2: part = sum_{i,j} 1/(1+d2) (diagonal removed later) ------
#define PART_BLOCK 256
#define PART_TILE  1024
#define PART_JCHUNKS (N_POINTS / PART_TILE)   // 16

__global__ __launch_bounds__(PART_BLOCK) void k_part() {
    __shared__ float2 tile[PART_TILE];
    __shared__ float sred[32];

    int i = blockIdx.x * PART_BLOCK + threadIdx.x;
    float2 xi = g_x[i];

    int j0 = blockIdx.y * PART_TILE;
    #pragma unroll
    for (int t = threadIdx.x; t < PART_TILE; t += PART_BLOCK)
        tile[t] = g_x[j0 + t];
    __syncthreads();

    float acc = 0.0f;
    #pragma unroll 8
    for (int t = 0; t < PART_TILE; t++) {
        float2 xj = tile[t];
        float da = xi.x - xj.x;
        float db = xi.y - xj.y;
        float d  = fmaf(da, da, fmaf(db, db, 1.0f));
        acc += rcp_fast(d);
    }

    float s = block_reduce(acc, sred);
    if (threadIdx.x == 0) atomicAdd(&g_part, (double)s);
}

// -------- kernel 3: pair loss: pij*(log pij + log(1+d2)), and sum(pij) ------
__global__ void k_pairs(const float* __restrict__ pij,
                        const int*   __restrict__ ii,
                        const int*   __restrict__ jj,
                        const float* __restrict__ mu,
                        const float* __restrict__ lv,
                        const float* __restrict__ epsi,
                        const float* __restrict__ epsj) {
    __shared__ float sred0[32];
    __shared__ float sred1[32];
    int p = blockIdx.x * blockDim.x + threadIdx.x;
    float term = 0.0f, psum = 0.0f;
    if (p < N_PAIRS) {
        int a = ii[p], b = jj[p];
        float2 ma = ((const float2*)mu)[a];
        float2 la = ((const float2*)lv)[a];
        float2 ea = ((const float2*)epsi)[p];
        float2 mb = ((const float2*)mu)[b];
        float2 lb = ((const float2*)lv)[b];
        float2 eb = ((const float2*)epsj)[p];
        float xax = fmaf(ea.x, expf(0.5f * la.x), ma.x);
        float xay = fmaf(ea.y, expf(0.5f * la.y), ma.y);
        float xbx = fmaf(eb.x, expf(0.5f * lb.x), mb.x);
        float xby = fmaf(eb.y, expf(0.5f * lb.y), mb.y);
        float da = xax - xbx, db = xay - xby;
        float d2 = fmaf(da, da, db * db);
        float pv = pij[p];
        // pij*(log pij - log qij) = pij*(log pij + log(1+d2) + log(part));
        // the log(part) piece is added in k_final via g_pijsum.
        term = pv * (logf(pv) + log1pf(d2));
        psum = pv;
    }
    float s0 = block_reduce(term, sred0);
    __syncthreads();
    float s1 = block_reduce(psum, sred1);
    if (threadIdx.x == 0) {
        atomicAdd(&g_pairloss, (double)s0);
        atomicAdd(&g_pijsum,  (double)s1);
    }
}

// -------- kernel 4: final combine -------------------------------------------
__global__ void k_final(float* __restrict__ out) {
    double part = g_part - (double)N_POINTS;  // remove diagonal (d2=0 -> 1 each)
    double loss = g_pairloss + g_pijsum * log(part) + 1e-7 * g_kld;
    out[0] = (float)loss;
}

// -----------------------------------------------------------------------------
extern "C" void kernel_launch(void* const* d_in, const int* in_sizes, int n_in,
                              void* d_out, int out_size) {
    const float* pij      = (const float*)d_in[0];
    const int*   i_idx    = (const int*)  d_in[1];
    const int*   j_idx    = (const int*)  d_in[2];
    const float* mu_w     = (const float*)d_in[3];
    const float* lv_w     = (const float*)d_in[4];
    const float* eps_full = (const float*)d_in[5];
    const float* eps_i    = (const float*)d_in[6];
    const float* eps_j    = (const float*)d_in[7];
    float* out = (float*)d_out;

    k_zero<<<1, 1>>>();
    k_reparam<<<N_POINTS / 256, 256>>>(mu_w, lv_w, eps_full);
    dim3 pgrid(N_POINTS / PART_BLOCK, PART_JCHUNKS);
    k_part<<<pgrid, PART_BLOCK>>>();
    k_pairs<<<N_PAIRS / 256, 256>>>(pij, i_idx, j_idx, mu_w, lv_w, eps_i, eps_j);
    k_final<<<1, 1>>>(out);
}

// round 2
// speedup vs baseline: 1.3695x; 1.3695x over previous
#include <cuda_runtime.h>
#include <math.h>

#define N_POINTS 16384
#define N_PAIRS  65536

#define PART_BLOCK 256
#define PART_TILE  1024
#define JCHUNKS    (N_POINTS / PART_TILE)     // 16
#define XBLOCKS    (N_POINTS / PART_BLOCK)    // 64
#define NPART_BLOCKS (XBLOCKS * JCHUNKS)      // 1024
#define PAIR_BLOCKS  64
#define REPARAM_BLOCKS (N_POINTS / 256)       // 64

typedef unsigned long long u64;
typedef unsigned int u32;

// ---- device scratch (no allocation allowed) --------------------------------
__device__ float g_xx[N_POINTS];
__device__ float g_xy[N_POINTS];
__device__ float g_cx[N_POINTS];   // 2*x.x
__device__ float g_cy[N_POINTS];   // 2*x.y
__device__ float g_nb[N_POINTS];   // -(1 + |x|^2)
__device__ float g_part_p[NPART_BLOCKS];
__device__ float g_kld_p[REPARAM_BLOCKS];
__device__ float g_pair_p[PAIR_BLOCKS];
__device__ float g_pij_p[PAIR_BLOCKS];

// ---- packed f32x2 helpers ----------------------------------------------------
__device__ __forceinline__ u64 pack2(float lo, float hi) {
    u64 r; asm("mov.b64 %0, {%1, %2};" : "=l"(r) : "f"(lo), "f"(hi)); return r;
}
__device__ __forceinline__ void unpack2f(float& lo, float& hi, u64 v) {
    asm("mov.b64 {%0, %1}, %2;" : "=f"(lo), "=f"(hi) : "l"(v));
}
__device__ __forceinline__ void unpack2u(u32& lo, u32& hi, u64 v) {
    asm("mov.b64 {%0, %1}, %2;" : "=r"(lo), "=r"(hi) : "l"(v));
}
__device__ __forceinline__ u64 pack2u(u32 lo, u32 hi) {
    u64 r; asm("mov.b64 %0, {%1, %2};" : "=l"(r) : "r"(lo), "r"(hi)); return r;
}
__device__ __forceinline__ u64 fma2(u64 a, u64 b, u64 c) {
    u64 d; asm("fma.rn.f32x2 %0, %1, %2, %3;" : "=l"(d) : "l"(a), "l"(b), "l"(c)); return d;
}
__device__ __forceinline__ u64 add2(u64 a, u64 b) {
    u64 d; asm("add.rn.f32x2 %0, %1, %2;" : "=l"(d) : "l"(a), "l"(b)); return d;
}

// ---- block reduction (float) -------------------------------------------------
__device__ __forceinline__ float block_reduce(float v, float* smem) {
    #pragma unroll
    for (int o = 16; o > 0; o >>= 1) v += __shfl_xor_sync(0xffffffffu, v, o);
    int lane = threadIdx.x & 31, wid = threadIdx.x >> 5;
    if (lane == 0) smem[wid] = v;
    __syncthreads();
    int nw = blockDim.x >> 5;
    v = (threadIdx.x < nw) ? smem[threadIdx.x] : 0.0f;
    if (wid == 0) {
        #pragma unroll
        for (int o = 16; o > 0; o >>= 1) v += __shfl_xor_sync(0xffffffffu, v, o);
    }
    return v;  // valid in thread 0
}

// ---- kernel 1: reparam + per-point precompute + KLD partials -----------------
__global__ void k_reparam(const float* __restrict__ mu,
                          const float* __restrict__ lv,
                          const float* __restrict__ eps) {
    __shared__ float sred[32];
    int idx = blockIdx.x * blockDim.x + threadIdx.x;
    float2 m = ((const float2*)mu)[idx];
    float2 l = ((const float2*)lv)[idx];
    float2 e = ((const float2*)eps)[idx];
    float elx = expf(l.x), ely = expf(l.y);
    float xx = fmaf(e.x, expf(0.5f * l.x), m.x);
    float xy = fmaf(e.y, expf(0.5f * l.y), m.y);
    g_xx[idx] = xx;
    g_xy[idx] = xy;
    g_cx[idx] = 2.0f * xx;
    g_cy[idx] = 2.0f * xy;
    g_nb[idx] = -fmaf(xx, xx, fmaf(xy, xy, 1.0f));
    float kld = (1.0f + l.x - m.x * m.x - elx)
              + (1.0f + l.y - m.y * m.y - ely);
    float s = block_reduce(kld, sred);
    if (threadIdx.x == 0) g_kld_p[blockIdx.x] = s;  // final applies -0.5
}

// ---- kernel 2: fused part (N^2) + pairs --------------------------------------
__global__ __launch_bounds__(PART_BLOCK)
void k_part_pairs(const float* __restrict__ pij,
                  const int*   __restrict__ ii,
                  const int*   __restrict__ jj,
                  const float* __restrict__ mu,
                  const float* __restrict__ lv,
                  const float* __restrict__ epsi,
                  const float* __restrict__ epsj) {
    __shared__ __align__(16) float scx[PART_TILE];
    __shared__ __align__(16) float scy[PART_TILE];
    __shared__ __align__(16) float snb[PART_TILE];
    __shared__ float sred[32];

    if (blockIdx.y < JCHUNKS) {
        // ---------------- part path: 256 i's x 1024 j's ----------------------
        int i = blockIdx.x * PART_BLOCK + threadIdx.x;
        float xix = g_xx[i], xiy = g_xy[i];
        float nh = -fmaf(xix, xix, xiy * xiy);  // -hi

        int j0 = blockIdx.y * PART_TILE;
        #pragma unroll
        for (int t = threadIdx.x; t < PART_TILE; t += PART_BLOCK) {
            scx[t] = g_cx[j0 + t];
            scy[t] = g_cy[j0 + t];
            snb[t] = g_nb[j0 + t];
        }
        __syncthreads();

        u64 xx2 = pack2(xix, xix);
        u64 xy2 = pack2(xiy, xiy);
        u64 nh2 = pack2(nh, nh);
        const u64 TWO2 = pack2(2.0f, 2.0f);
        u64 acc = pack2(0.0f, 0.0f);

        #pragma unroll 8
        for (int t = 0; t < PART_TILE; t += 2) {
            u64 cx2 = *(const u64*)(scx + t);
            u64 cy2 = *(const u64*)(scy + t);
            u64 nb2 = *(const u64*)(snb + t);
            // nd = 2*xi.xj - (1 + hi + hj)  (== -d, d >= 1)
            u64 s  = add2(nb2, nh2);
            s      = fma2(xy2, cy2, s);
            u64 nd = fma2(xx2, cx2, s);
            // magic rcp seed: bits(d) = bits(nd) - 0x80000000 (sign flip)
            u32 ndl, ndh; unpack2u(ndl, ndh, nd);
            u32 y0l = 0xFEF127EAu - ndl;
            u32 y0h = 0xFEF127EAu - ndh;
            u64 y0 = pack2u(y0l, y0h);
            // one Newton step folded into the accumulate:
            // y1 = y0*(2 - d*y0) = y0*(2 + nd*y0);  acc += y1
            u64 tt = fma2(nd, y0, TWO2);
            acc = fma2(y0, tt, acc);
        }

        float al, ah; unpack2f(al, ah, acc);
        float s = block_reduce(al + ah, sred);
        if (threadIdx.x == 0)
            g_part_p[blockIdx.y * XBLOCKS + blockIdx.x] = s;
    } else {
        // ---------------- pairs path: 64 blocks x 1024 pairs -----------------
        __shared__ float sred1[32];
        float term = 0.0f, psum = 0.0f;
        int base = blockIdx.x * 1024;
        #pragma unroll
        for (int r = 0; r < 4; r++) {
            int p = base + r * PART_BLOCK + threadIdx.x;
            int a = ii[p], b = jj[p];
            float2 ma = ((const float2*)mu)[a];
            float2 la = ((const float2*)lv)[a];
            float2 ea = ((const float2*)epsi)[p];
            float2 mb = ((const float2*)mu)[b];
            float2 lb = ((const float2*)lv)[b];
            float2 eb = ((const float2*)epsj)[p];
            float xax = fmaf(ea.x, expf(0.5f * la.x), ma.x);
            float xay = fmaf(ea.y, expf(0.5f * la.y), ma.y);
            float xbx = fmaf(eb.x, expf(0.5f * lb.x), mb.x);
            float xby = fmaf(eb.y, expf(0.5f * lb.y), mb.y);
            float da = xax - xbx, db = xay - xby;
            float d2 = fmaf(da, da, db * db);
            float pv = pij[p];
            // pij*(log pij - log qij) = pij*(log pij + log(1+d2)) + pij*log(part)
            term += pv * (logf(pv) + log1pf(d2));
            psum += pv;
        }
        float s0 = block_reduce(term, sred);
        __syncthreads();
        float s1 = block_reduce(psum, sred1);
        if (threadIdx.x == 0) {
            g_pair_p[blockIdx.x] = s0;
            g_pij_p[blockIdx.x]  = s1;
        }
    }
}

// ---- kernel 3: final deterministic reduce + combine --------------------------
__global__ void k_final(float* __restrict__ out) {
    __shared__ double sd[256];
    int tid = threadIdx.x;

    double part = 0.0, kld = 0.0, pair = 0.0, pijs = 0.0;
    for (int t = tid; t < NPART_BLOCKS; t += 256) part += (double)g_part_p[t];
    if (tid < REPARAM_BLOCKS) kld  = (double)g_kld_p[tid];
    if (tid < PAIR_BLOCKS)    pair = (double)g_pair_p[tid];
    if (tid < PAIR_BLOCKS)    pijs = (double)g_pij_p[tid];

    // reduce 4 values; pack sequentially through shared memory
    double vals[4] = {part, kld, pair, pijs};
    double res[4];
    #pragma unroll
    for (int k = 0; k < 4; k++) {
        sd[tid] = vals[k];
        __syncthreads();
        for (int o = 128; o > 0; o >>= 1) {
            if (tid < o) sd[tid] += sd[tid + o];
            __syncthreads();
        }
        res[k] = sd[0];
        __syncthreads();
    }

    if (tid == 0) {
        double partv = res[0] - (double)N_POINTS;  // remove diagonal
        double loss = res[2] + res[3] * log(partv) + 1e-7 * (-0.5 * res[1]);
        out[0] = (float)loss;
    }
}

// -----------------------------------------------------------------------------
extern "C" void kernel_launch(void* const* d_in, const int* in_sizes, int n_in,
                              void* d_out, int out_size) {
    const float* pij      = (const float*)d_in[0];
    const int*   i_idx    = (const int*)  d_in[1];
    const int*   j_idx    = (const int*)  d_in[2];
    const float* mu_w     = (const float*)d_in[3];
    const float* lv_w     = (const float*)d_in[4];
    const float* eps_full = (const float*)d_in[5];
    const float* eps_i    = (const float*)d_in[6];
    const float* eps_j    = (const float*)d_in[7];
    float* out = (float*)d_out;

    k_reparam<<<REPARAM_BLOCKS, 256>>>(mu_w, lv_w, eps_full);
    dim3 pgrid(XBLOCKS, JCHUNKS + 1);   // y = 0..15 part tiles, y = 16 pairs
    k_part_pairs<<<pgrid, PART_BLOCK>>>(pij, i_idx, j_idx, mu_w, lv_w, eps_i, eps_j);
    k_final<<<1, 256>>>(out);
}

// round 3
// speedup vs baseline: 2.3345x; 1.7046x over previous
#include <cuda_runtime.h>
#include <math.h>

#define N_POINTS 16384
#define N_PAIRS  65536

#define T_SUPER  16                      // 16 supertiles of 1024 points
#define N_SUPER  136                     // T*(T+1)/2 upper-triangle supertiles
#define HEAVY_BLOCKS (N_SUPER * 2)       // 272: each CTA = 512 i x 1024 j
#define PAIR_BLOCKS  64
#define NBLOCKS  (HEAVY_BLOCKS + PAIR_BLOCKS)   // 336
#define REPARAM_BLOCKS (N_POINTS / 256)  // 64
#define KLD_PARTS (N_POINTS / 32)        // 512 (per-warp partials)

typedef unsigned long long u64;
typedef unsigned int u32;

// ---- device scratch (no allocation allowed) --------------------------------
__device__ float  g_xx[N_POINTS];
__device__ float  g_xy[N_POINTS];
__device__ float4 g_cxy[N_POINTS / 2];   // per j-pair: (cx0, cx1, cy0, cy1)
__device__ float2 g_nb2[N_POINTS / 2];   // per j-pair: (nb0, nb1), nb = -(1+|x|^2)
__device__ float  g_part_p[HEAVY_BLOCKS];
__device__ float  g_kld_p[KLD_PARTS];
__device__ float  g_pair_p[PAIR_BLOCKS];
__device__ float  g_pij_p[PAIR_BLOCKS];
__device__ unsigned int g_ticket = 0;

// ---- packed f32x2 helpers ---------------------------------------------------
__device__ __forceinline__ u64 pack2(float lo, float hi) {
    u64 r; asm("mov.b64 %0, {%1, %2};" : "=l"(r) : "f"(lo), "f"(hi)); return r;
}
__device__ __forceinline__ void unpack2f(float& lo, float& hi, u64 v) {
    asm("mov.b64 {%0, %1}, %2;" : "=f"(lo), "=f"(hi) : "l"(v));
}
__device__ __forceinline__ u64 fma2(u64 a, u64 b, u64 c) {
    u64 d; asm("fma.rn.f32x2 %0, %1, %2, %3;" : "=l"(d) : "l"(a), "l"(b), "l"(c)); return d;
}
__device__ __forceinline__ u64 add2(u64 a, u64 b) {
    u64 d; asm("add.rn.f32x2 %0, %1, %2;" : "=l"(d) : "l"(a), "l"(b)); return d;
}

// ---- warp/block reduction ---------------------------------------------------
__device__ __forceinline__ float warp_reduce(float v) {
    #pragma unroll
    for (int o = 16; o > 0; o >>= 1) v += __shfl_xor_sync(0xffffffffu, v, o);
    return v;
}
__device__ __forceinline__ float block_reduce(float v, float* smem) {
    v = warp_reduce(v);
    int lane = threadIdx.x & 31, wid = threadIdx.x >> 5;
    if (lane == 0) smem[wid] = v;
    __syncthreads();
    v = (threadIdx.x < 8) ? smem[threadIdx.x] : 0.0f;
    if (wid == 0) {
        #pragma unroll
        for (int o = 4; o > 0; o >>= 1) v += __shfl_xor_sync(0xffffffffu, v, o);
    }
    return v;  // valid in thread 0
}

// ---- kernel 1: reparam + precompute + per-warp KLD partials ------------------
__global__ void k_reparam(const float* __restrict__ mu,
                          const float* __restrict__ lv,
                          const float* __restrict__ eps) {
    int idx = blockIdx.x * 256 + threadIdx.x;
    float2 m = ((const float2*)mu)[idx];
    float2 l = ((const float2*)lv)[idx];
    float2 e = ((const float2*)eps)[idx];
    float sx = __expf(0.5f * l.x), sy = __expf(0.5f * l.y);
    float xx = fmaf(e.x, sx, m.x);
    float xy = fmaf(e.y, sy, m.y);
    g_xx[idx] = xx;
    g_xy[idx] = xy;
    float cx = 2.0f * xx, cy = 2.0f * xy;
    float nb = -fmaf(xx, xx, fmaf(xy, xy, 1.0f));
    // pack j-pair layout via shfl (even lanes write pair p = idx/2)
    float cxn = __shfl_down_sync(0xffffffffu, cx, 1);
    float cyn = __shfl_down_sync(0xffffffffu, cy, 1);
    float nbn = __shfl_down_sync(0xffffffffu, nb, 1);
    if ((threadIdx.x & 1) == 0) {
        int p = idx >> 1;
        g_cxy[p] = make_float4(cx, cxn, cy, cyn);
        g_nb2[p] = make_float2(nb, nbn);
    }
    float kld = (1.0f + l.x - m.x * m.x - sx * sx)
              + (1.0f + l.y - m.y * m.y - sy * sy);
    kld = warp_reduce(kld);
    if ((threadIdx.x & 31) == 0) g_kld_p[idx >> 5] = kld;
}

// ---- kernel 2: symmetric part + pairs + fused final ---------------------------
__global__ __launch_bounds__(256)
void k_main(const float* __restrict__ pij,
            const int*   __restrict__ ii,
            const int*   __restrict__ jj,
            const float* __restrict__ mu,
            const float* __restrict__ lv,
            const float* __restrict__ epsi,
            const float* __restrict__ epsj,
            float* __restrict__ out) {
    __shared__ __align__(16) ulonglong2 s_cxy[512];  // per pair: (cx01, cy01)
    __shared__ __align__(16) u64        s_nb2[512];
    __shared__ float  sred[8];
    __shared__ float  sred1[8];
    __shared__ double sdd[256];
    __shared__ unsigned int s_last;

    const int bid = blockIdx.x;
    const int tid = threadIdx.x;

    if (bid < HEAVY_BLOCKS) {
        // -------- heavy path: supertile (a,b), half = bid&1 -----------------
        int s = bid >> 1;
        int a = 0, rem = s;
        while (rem >= T_SUPER - a) { rem -= T_SUPER - a; a++; }
        int b = a + rem;
        int i0 = a * 1024 + (bid & 1) * 512;
        int j0 = b * 1024;
        float wt = (a == b) ? 1.0f : 2.0f;

        // load j-tile (512 pairs) into shared
        {
            const float4* gc = g_cxy + (j0 >> 1);
            const float2* gn = g_nb2 + (j0 >> 1);
            #pragma unroll
            for (int t = tid; t < 512; t += 256) {
                float4 v = gc[t];
                ulonglong2 w;
                w.x = pack2(v.x, v.y);   // (cx0, cx1)
                w.y = pack2(v.z, v.w);   // (cy0, cy1)
                s_cxy[t] = w;
                float2 n = gn[t];
                s_nb2[t] = pack2(n.x, n.y);
            }
        }

        // i-register blocking x2
        int ia = i0 + tid, ib = i0 + 256 + tid;
        float xax = g_xx[ia], xay = g_xy[ia];
        float xbx = g_xx[ib], xby = g_xy[ib];
        u64 xax2 = pack2(xax, xax), xay2 = pack2(xay, xay);
        u64 xbx2 = pack2(xbx, xbx), xby2 = pack2(xby, xby);
        u64 nha = pack2(-fmaf(xax, xax, xay * xay), -fmaf(xax, xax, xay * xay));
        u64 nhb = pack2(-fmaf(xbx, xbx, xby * xby), -fmaf(xbx, xbx, xby * xby));
        const u64 TWO2 = pack2(2.0f, 2.0f);
        const u64 MAGIC2 = 0xFEF127EAFEF127EAull;
        u64 acc0 = 0ull, acc1 = 0ull;

        __syncthreads();

        #pragma unroll 8
        for (int p = 0; p < 512; p++) {
            ulonglong2 v = s_cxy[p];   // LDS.128: cx pair, cy pair
            u64 nb2 = s_nb2[p];        // LDS.64
            // i = ia
            u64 s0 = add2(nb2, nha);
            s0 = fma2(v.y, xay2, s0);
            u64 nd0 = fma2(v.x, xax2, s0);       // nd = -(1+d2), d2>=0
            u64 y00 = MAGIC2 - nd0;              // magic rcp seed (both halves, no borrow)
            acc0 = fma2(y00, fma2(nd0, y00, TWO2), acc0);
            // i = ib
            u64 s1 = add2(nb2, nhb);
            s1 = fma2(v.y, xby2, s1);
            u64 nd1 = fma2(v.x, xbx2, s1);
            u64 y01 = MAGIC2 - nd1;
            acc1 = fma2(y01, fma2(nd1, y01, TWO2), acc1);
        }

        float a0l, a0h, a1l, a1h;
        unpack2f(a0l, a0h, acc0);
        unpack2f(a1l, a1h, acc1);
        float sres = block_reduce((a0l + a0h) + (a1l + a1h), sred);
        if (tid == 0) g_part_p[bid] = sres * wt;
    } else {
        // -------- pairs path -------------------------------------------------
        int pb = bid - HEAVY_BLOCKS;
        float term = 0.0f, psum = 0.0f;
        int base = pb * 1024;
        #pragma unroll
        for (int r = 0; r < 4; r++) {
            int p = base + r * 256 + tid;
            int ai = ii[p], bi = jj[p];
            float2 ma = ((const float2*)mu)[ai];
            float2 la = ((const float2*)lv)[ai];
            float2 ea = ((const float2*)epsi)[p];
            float2 mb = ((const float2*)mu)[bi];
            float2 lb = ((const float2*)lv)[bi];
            float2 eb = ((const float2*)epsj)[p];
            float xax = fmaf(ea.x, __expf(0.5f * la.x), ma.x);
            float xay = fmaf(ea.y, __expf(0.5f * la.y), ma.y);
            float xbx = fmaf(eb.x, __expf(0.5f * lb.x), mb.x);
            float xby = fmaf(eb.y, __expf(0.5f * lb.y), mb.y);
            float da = xax - xbx, db = xay - xby;
            float d2 = fmaf(da, da, db * db);
            float pv = pij[p];
            // pij*(log pij - log qij) = pij*(log pij + log(1+d2)) + pij*log(part)
            term += pv * (logf(pv) + log1pf(d2));
            psum += pv;
        }
        float s0 = block_reduce(term, sred);
        __syncthreads();
        float s1 = block_reduce(psum, sred1);
        if (tid == 0) {
            g_pair_p[pb] = s0;
            g_pij_p[pb]  = s1;
        }
    }

    // -------- fused final: last CTA reduces everything ------------------------
    __threadfence();
    if (tid == 0) s_last = atomicAdd(&g_ticket, 1u);
    __syncthreads();
    if (s_last == NBLOCKS - 1) {
        __threadfence();
        double part = 0.0, kld = 0.0, pair = 0.0, pijs = 0.0;
        for (int t = tid; t < HEAVY_BLOCKS; t += 256) part += (double)g_part_p[t];
        for (int t = tid; t < KLD_PARTS;    t += 256) kld  += (double)g_kld_p[t];
        if (tid < PAIR_BLOCKS) { pair = (double)g_pair_p[tid]; pijs = (double)g_pij_p[tid]; }

        double vals[4] = {part, kld, pair, pijs};
        double res[4];
        #pragma unroll
        for (int k = 0; k < 4; k++) {
            sdd[tid] = vals[k];
            __syncthreads();
            for (int o = 128; o > 0; o >>= 1) {
                if (tid < o) sdd[tid] += sdd[tid + o];
                __syncthreads();
            }
            res[k] = sdd[0];
            __syncthreads();
        }
        if (tid == 0) {
            double partv = res[0] - (double)N_POINTS;  // remove diagonal
            double loss = res[2] + res[3] * log(partv) + 1e-7 * (-0.5 * res[1]);
            out[0] = (float)loss;
            g_ticket = 0;  // reset for next replay
        }
    }
}

// -----------------------------------------------------------------------------
extern "C" void kernel_launch(void* const* d_in, const int* in_sizes, int n_in,
                              void* d_out, int out_size) {
    const float* pij      = (const float*)d_in[0];
    const int*   i_idx    = (const int*)  d_in[1];
    const int*   j_idx    = (const int*)  d_in[2];
    const float* mu_w     = (const float*)d_in[3];
    const float* lv_w     = (const float*)d_in[4];
    const float* eps_full = (const float*)d_in[5];
    const float* eps_i    = (const float*)d_in[6];
    const float* eps_j    = (const float*)d_in[7];
    float* out = (float*)d_out;

    k_reparam<<<REPARAM_BLOCKS, 256>>>(mu_w, lv_w, eps_full);
    k_main<<<NBLOCKS, 256>>>(pij, i_idx, j_idx, mu_w, lv_w, eps_i, eps_j, out);
}

// round 4
// speedup vs baseline: 2.4366x; 1.0437x over previous
#include <cuda_runtime.h>
#include <math.h>

#define N_POINTS 16384
#define N_PAIRS  65536

#define T_SUPER  16                      // 16 supertiles of 1024 points
#define N_SUPER  136                     // T*(T+1)/2 upper-triangle supertiles
#define SUBS_PER_SUPER 8                 // 2 i-halves (512) x 4 j-quarters (256)
#define HEAVY_BLOCKS (N_SUPER * SUBS_PER_SUPER)  // 1088
#define PAIR_BLOCKS  64
#define NBLOCKS  (HEAVY_BLOCKS + PAIR_BLOCKS)    // 1152
#define JTILE 256                        // j points per heavy CTA
#define JPAIRS (JTILE / 2)               // 128

typedef unsigned long long u64;
typedef unsigned int u32;

// ---- device scratch (no allocation allowed) ----------------------------------
__device__ float g_part_p[HEAVY_BLOCKS];
__device__ float g_kld_p[PAIR_BLOCKS];
__device__ float g_pair_p[PAIR_BLOCKS];
__device__ float g_pij_p[PAIR_BLOCKS];
__device__ unsigned int g_ticket = 0;

// ---- packed f32x2 helpers -----------------------------------------------------
__device__ __forceinline__ u64 pack2(float lo, float hi) {
    u64 r; asm("mov.b64 %0, {%1, %2};" : "=l"(r) : "f"(lo), "f"(hi)); return r;
}
__device__ __forceinline__ void unpack2f(float& lo, float& hi, u64 v) {
    asm("mov.b64 {%0, %1}, %2;" : "=f"(lo), "=f"(hi) : "l"(v));
}
__device__ __forceinline__ u64 fma2(u64 a, u64 b, u64 c) {
    u64 d; asm("fma.rn.f32x2 %0, %1, %2, %3;" : "=l"(d) : "l"(a), "l"(b), "l"(c)); return d;
}
__device__ __forceinline__ u64 add2(u64 a, u64 b) {
    u64 d; asm("add.rn.f32x2 %0, %1, %2;" : "=l"(d) : "l"(a), "l"(b)); return d;
}

// ---- reductions ----------------------------------------------------------------
__device__ __forceinline__ float warp_reduce(float v) {
    #pragma unroll
    for (int o = 16; o > 0; o >>= 1) v += __shfl_xor_sync(0xffffffffu, v, o);
    return v;
}
__device__ __forceinline__ float block_reduce(float v, float* smem) {
    v = warp_reduce(v);
    int lane = threadIdx.x & 31, wid = threadIdx.x >> 5;
    if (lane == 0) smem[wid] = v;
    __syncthreads();
    v = (threadIdx.x < 8) ? smem[threadIdx.x] : 0.0f;
    if (wid == 0) {
        #pragma unroll
        for (int o = 4; o > 0; o >>= 1) v += __shfl_xor_sync(0xffffffffu, v, o);
    }
    return v;  // valid in thread 0
}

// ---- reparam helper: x = eps*exp(0.5*lv) + mu ----------------------------------
__device__ __forceinline__ float2 reparam_pt(const float* __restrict__ mu,
                                             const float* __restrict__ lv,
                                             const float* __restrict__ eps,
                                             int idx) {
    float2 m = ((const float2*)mu)[idx];
    float2 l = ((const float2*)lv)[idx];
    float2 e = ((const float2*)eps)[idx];
    float2 x;
    x.x = fmaf(e.x, __expf(0.5f * l.x), m.x);
    x.y = fmaf(e.y, __expf(0.5f * l.y), m.y);
    return x;
}

// ---- single fused kernel --------------------------------------------------------
__global__ __launch_bounds__(256)
void k_main(const float* __restrict__ pij,
            const int*   __restrict__ ii,
            const int*   __restrict__ jj,
            const float* __restrict__ mu,
            const float* __restrict__ lv,
            const float* __restrict__ epsf,
            const float* __restrict__ epsi,
            const float* __restrict__ epsj,
            float* __restrict__ out) {
    __shared__ __align__(16) ulonglong2 s_cxy[JPAIRS];  // per j-pair: (cx01, cy01)
    __shared__ __align__(16) u64        s_nb2[JPAIRS];  // per j-pair: (nb0, nb1)
    __shared__ float  sred[8];
    __shared__ float  sred1[8];
    __shared__ double sdd[256];
    __shared__ unsigned int s_last;

    const int bid = blockIdx.x;
    const int tid = threadIdx.x;

    if (bid < HEAVY_BLOCKS) {
        // -------- heavy path: supertile s, sub-block (i-half, j-quarter) --------
        int s = bid >> 3;
        int sub = bid & 7;
        int a = 0, rem = s;
        while (rem >= T_SUPER - a) { rem -= T_SUPER - a; a++; }
        int b = a + rem;
        int i0 = a * 1024 + (sub >> 2) * 512;
        int j0 = b * 1024 + (sub & 3)  * JTILE;
        float wt = (a == b) ? 1.0f : 2.0f;

        // build j-tile in shared from raw inputs (reparam on the fly)
        {
            float2 xj = reparam_pt(mu, lv, epsf, j0 + tid);
            float cx = 2.0f * xj.x, cy = 2.0f * xj.y;
            float nb = -fmaf(xj.x, xj.x, fmaf(xj.y, xj.y, 1.0f));
            float cxn = __shfl_down_sync(0xffffffffu, cx, 1);
            float cyn = __shfl_down_sync(0xffffffffu, cy, 1);
            float nbn = __shfl_down_sync(0xffffffffu, nb, 1);
            if ((tid & 1) == 0) {
                int p = tid >> 1;
                ulonglong2 w;
                w.x = pack2(cx, cxn);
                w.y = pack2(cy, cyn);
                s_cxy[p] = w;
                s_nb2[p] = pack2(nb, nbn);
            }
        }

        // i register-blocking x2 (512 i per CTA)
        float2 xa = reparam_pt(mu, lv, epsf, i0 + tid);
        float2 xb = reparam_pt(mu, lv, epsf, i0 + 256 + tid);
        u64 xax2 = pack2(xa.x, xa.x), xay2 = pack2(xa.y, xa.y);
        u64 xbx2 = pack2(xb.x, xb.x), xby2 = pack2(xb.y, xb.y);
        float nhaf = -fmaf(xa.x, xa.x, xa.y * xa.y);
        float nhbf = -fmaf(xb.x, xb.x, xb.y * xb.y);
        u64 nha = pack2(nhaf, nhaf);
        u64 nhb = pack2(nhbf, nhbf);
        const u64 TWO2 = pack2(2.0f, 2.0f);
        const u64 MAGIC2 = 0xFEF127EAFEF127EAull;
        u64 acc0 = 0ull, acc1 = 0ull;

        __syncthreads();

        #pragma unroll 8
        for (int p = 0; p < JPAIRS; p++) {
            ulonglong2 v = s_cxy[p];   // LDS.128
            u64 nb2 = s_nb2[p];        // LDS.64
            // nd = 2*xi.xj - (1 + hi + hj) = -(1 + d2)
            u64 s0 = add2(nb2, nha);
            s0 = fma2(v.y, xay2, s0);
            u64 nd0 = fma2(v.x, xax2, s0);
            u64 y00 = MAGIC2 - nd0;                    // packed magic rcp seed
            acc0 = fma2(y00, fma2(nd0, y00, TWO2), acc0);  // Newton + accumulate

            u64 s1 = add2(nb2, nhb);
            s1 = fma2(v.y, xby2, s1);
            u64 nd1 = fma2(v.x, xbx2, s1);
            u64 y01 = MAGIC2 - nd1;
            acc1 = fma2(y01, fma2(nd1, y01, TWO2), acc1);
        }

        float a0l, a0h, a1l, a1h;
        unpack2f(a0l, a0h, acc0);
        unpack2f(a1l, a1h, acc1);
        float sres = block_reduce((a0l + a0h) + (a1l + a1h), sred);
        if (tid == 0) g_part_p[bid] = sres * wt;
    } else {
        // -------- pairs path + KLD slice -----------------------------------------
        int pb = bid - HEAVY_BLOCKS;
        float term = 0.0f, psum = 0.0f;
        int base = pb * 1024;
        #pragma unroll
        for (int r = 0; r < 4; r++) {
            int p = base + r * 256 + tid;
            int ai = ii[p], bi = jj[p];
            float2 xai = reparam_pt(mu, lv, epsi - 0, 0), dummy;  // (unused pattern guard)
            (void)xai; (void)dummy;
            float2 ma = ((const float2*)mu)[ai];
            float2 la = ((const float2*)lv)[ai];
            float2 ea = ((const float2*)epsi)[p];
            float2 mb = ((const float2*)mu)[bi];
            float2 lb = ((const float2*)lv)[bi];
            float2 eb = ((const float2*)epsj)[p];
            float xax = fmaf(ea.x, __expf(0.5f * la.x), ma.x);
            float xay = fmaf(ea.y, __expf(0.5f * la.y), ma.y);
            float xbx = fmaf(eb.x, __expf(0.5f * lb.x), mb.x);
            float xby = fmaf(eb.y, __expf(0.5f * lb.y), mb.y);
            float da = xax - xbx, db = xay - xby;
            float d2 = fmaf(da, da, db * db);
            float pv = pij[p];
            // pij*(log pij - log qij) = pij*(log pij + log(1+d2)) + pij*log(part)
            term += pv * (logf(pv) + log1pf(d2));
            psum += pv;
        }
        // KLD slice: 256 points per pair-block (64 * 256 = 16384)
        float kld;
        {
            int idx = pb * 256 + tid;
            float2 m = ((const float2*)mu)[idx];
            float2 l = ((const float2*)lv)[idx];
            kld = (1.0f + l.x - m.x * m.x - __expf(l.x))
                + (1.0f + l.y - m.y * m.y - __expf(l.y));
        }
        float s0 = block_reduce(term, sred);
        __syncthreads();
        float s1 = block_reduce(psum, sred1);
        __syncthreads();
        float s2 = block_reduce(kld, sred);
        if (tid == 0) {
            g_pair_p[pb] = s0;
            g_pij_p[pb]  = s1;
            g_kld_p[pb]  = s2;
        }
    }

    // -------- fused final: last CTA reduces everything ----------------------------
    __threadfence();
    if (tid == 0) s_last = atomicAdd(&g_ticket, 1u);
    __syncthreads();
    if (s_last == NBLOCKS - 1) {
        __threadfence();
        double part = 0.0, kld = 0.0, pair = 0.0, pijs = 0.0;
        for (int t = tid; t < HEAVY_BLOCKS; t += 256) part += (double)g_part_p[t];
        if (tid < PAIR_BLOCKS) {
            kld  = (double)g_kld_p[tid];
            pair = (double)g_pair_p[tid];
            pijs = (double)g_pij_p[tid];
        }
        double vals[4] = {part, kld, pair, pijs};
        double res[4];
        #pragma unroll
        for (int k = 0; k < 4; k++) {
            sdd[tid] = vals[k];
            __syncthreads();
            for (int o = 128; o > 0; o >>= 1) {
                if (tid < o) sdd[tid] += sdd[tid + o];
                __syncthreads();
            }
            res[k] = sdd[0];
            __syncthreads();
        }
        if (tid == 0) {
            double partv = res[0] - (double)N_POINTS;   // remove diagonal
            double loss = res[2] + res[3] * log(partv) + 1e-7 * (-0.5 * res[1]);
            out[0] = (float)loss;
            g_ticket = 0;   // reset for next graph replay
        }
    }
}

// -----------------------------------------------------------------------------
extern "C" void kernel_launch(void* const* d_in, const int* in_sizes, int n_in,
                              void* d_out, int out_size) {
    const float* pij      = (const float*)d_in[0];
    const int*   i_idx    = (const int*)  d_in[1];
    const int*   j_idx    = (const int*)  d_in[2];
    const float* mu_w     = (const float*)d_in[3];
    const float* lv_w     = (const float*)d_in[4];
    const float* eps_full = (const float*)d_in[5];
    const float* eps_i    = (const float*)d_in[6];
    const float* eps_j    = (const float*)d_in[7];
    float* out = (float*)d_out;

    k_main<<<NBLOCKS, 256>>>(pij, i_idx, j_idx, mu_w, lv_w,
                             eps_full, eps_i, eps_j, out);
}

// round 5
// speedup vs baseline: 2.4581x; 1.0088x over previous
#include <cuda_runtime.h>
#include <math.h>

#define N_POINTS 16384
#define N_PAIRS  65536

#define T_SUPER  16                      // 16 supertiles of 1024 points
#define N_SUPER  136                     // T*(T+1)/2 upper-triangle supertiles
#define SUBS_PER_SUPER 4                 // 2 i-halves (512) x 2 j-halves (512)
#define HEAVY_BLOCKS (N_SUPER * SUBS_PER_SUPER)  // 544
#define PAIR_BLOCKS  64
#define NBLOCKS  (HEAVY_BLOCKS + PAIR_BLOCKS)    // 608  (single wave @ >=5 CTA/SM)
#define JTILE 512                        // j points per heavy CTA
#define JPAIRS (JTILE / 2)               // 256

typedef unsigned long long u64;
typedef unsigned int u32;

// ---- device scratch (no allocation allowed) ----------------------------------
__device__ float g_part_p[HEAVY_BLOCKS];
__device__ float g_kld_p[PAIR_BLOCKS];
__device__ float g_pair_p[PAIR_BLOCKS];
__device__ float g_pij_p[PAIR_BLOCKS];
__device__ unsigned int g_ticket = 0;

// ---- packed f32x2 helpers -----------------------------------------------------
__device__ __forceinline__ u64 pack2(float lo, float hi) {
    u64 r; asm("mov.b64 %0, {%1, %2};" : "=l"(r) : "f"(lo), "f"(hi)); return r;
}
__device__ __forceinline__ void unpack2f(float& lo, float& hi, u64 v) {
    asm("mov.b64 {%0, %1}, %2;" : "=f"(lo), "=f"(hi) : "l"(v));
}
__device__ __forceinline__ u64 fma2(u64 a, u64 b, u64 c) {
    u64 d; asm("fma.rn.f32x2 %0, %1, %2, %3;" : "=l"(d) : "l"(a), "l"(b), "l"(c)); return d;
}
__device__ __forceinline__ u64 add2(u64 a, u64 b) {
    u64 d; asm("add.rn.f32x2 %0, %1, %2;" : "=l"(d) : "l"(a), "l"(b)); return d;
}

// ---- reductions ----------------------------------------------------------------
__device__ __forceinline__ float warp_reduce(float v) {
    #pragma unroll
    for (int o = 16; o > 0; o >>= 1) v += __shfl_xor_sync(0xffffffffu, v, o);
    return v;
}
__device__ __forceinline__ float block_reduce(float v, float* smem) {
    v = warp_reduce(v);
    int lane = threadIdx.x & 31, wid = threadIdx.x >> 5;
    if (lane == 0) smem[wid] = v;
    __syncthreads();
    v = (threadIdx.x < 8) ? smem[threadIdx.x] : 0.0f;
    if (wid == 0) {
        #pragma unroll
        for (int o = 4; o > 0; o >>= 1) v += __shfl_xor_sync(0xffffffffu, v, o);
    }
    return v;  // valid in thread 0
}

// ---- reparam helper: x = eps*exp(0.5*lv) + mu ----------------------------------
__device__ __forceinline__ float2 reparam_pt(const float* __restrict__ mu,
                                             const float* __restrict__ lv,
                                             const float* __restrict__ eps,
                                             int idx) {
    float2 m = ((const float2*)mu)[idx];
    float2 l = ((const float2*)lv)[idx];
    float2 e = ((const float2*)eps)[idx];
    float2 x;
    x.x = fmaf(e.x, __expf(0.5f * l.x), m.x);
    x.y = fmaf(e.y, __expf(0.5f * l.y), m.y);
    return x;
}

// ---- single fused kernel --------------------------------------------------------
__global__ __launch_bounds__(256, 6)
void k_main(const float* __restrict__ pij,
            const int*   __restrict__ ii,
            const int*   __restrict__ jj,
            const float* __restrict__ mu,
            const float* __restrict__ lv,
            const float* __restrict__ epsf,
            const float* __restrict__ epsi,
            const float* __restrict__ epsj,
            float* __restrict__ out) {
    __shared__ __align__(16) ulonglong2 s_cxy[JPAIRS + 2];  // per j-pair: (cx01, cy01)
    __shared__ __align__(16) u64        s_nb2[JPAIRS + 2];  // per j-pair: (nb0, nb1)
    __shared__ float  sred[8];
    __shared__ float  sred1[8];
    __shared__ double sdd[256];
    __shared__ unsigned int s_last;

    const int bid = blockIdx.x;
    const int tid = threadIdx.x;

    if (bid < HEAVY_BLOCKS) {
        // -------- heavy path: supertile s, sub-block (i-half, j-half) ------------
        int s = bid >> 2;
        int sub = bid & 3;
        int a = 0, rem = s;
        while (rem >= T_SUPER - a) { rem -= T_SUPER - a; a++; }
        int b = a + rem;
        int i0 = a * 1024 + (sub >> 1) * 512;
        int j0 = b * 1024 + (sub & 1)  * JTILE;
        float wt = (a == b) ? 1.0f : 2.0f;

        // build j-tile in shared from raw inputs (reparam on the fly): 512 j's
        #pragma unroll
        for (int r = 0; r < 2; r++) {
            int jj_ = j0 + r * 256 + tid;
            float2 xj = reparam_pt(mu, lv, epsf, jj_);
            float cx = 2.0f * xj.x, cy = 2.0f * xj.y;
            float nb = -fmaf(xj.x, xj.x, fmaf(xj.y, xj.y, 1.0f));
            float cxn = __shfl_down_sync(0xffffffffu, cx, 1);
            float cyn = __shfl_down_sync(0xffffffffu, cy, 1);
            float nbn = __shfl_down_sync(0xffffffffu, nb, 1);
            if ((tid & 1) == 0) {
                int p = (r * 256 + tid) >> 1;
                ulonglong2 w;
                w.x = pack2(cx, cxn);
                w.y = pack2(cy, cyn);
                s_cxy[p] = w;
                s_nb2[p] = pack2(nb, nbn);
            }
        }
        if (tid < 2) {  // pad for prefetch overread
            s_cxy[JPAIRS + tid] = make_ulonglong2(0ull, 0ull);
            s_nb2[JPAIRS + tid] = pack2(-1.0f, -1.0f);
        }

        // i register-blocking x2 (512 i per CTA)
        float2 xa = reparam_pt(mu, lv, epsf, i0 + tid);
        float2 xb = reparam_pt(mu, lv, epsf, i0 + 256 + tid);
        u64 xax2 = pack2(xa.x, xa.x), xay2 = pack2(xa.y, xa.y);
        u64 xbx2 = pack2(xb.x, xb.x), xby2 = pack2(xb.y, xb.y);
        float nhaf = -fmaf(xa.x, xa.x, xa.y * xa.y);
        float nhbf = -fmaf(xb.x, xb.x, xb.y * xb.y);
        u64 nha = pack2(nhaf, nhaf);
        u64 nhb = pack2(nhbf, nhbf);
        const u64 TWO2 = pack2(2.0f, 2.0f);
        const u64 MAGIC2 = 0xFEF127EAFEF127EAull;
        u64 acc0 = 0ull, acc1 = 0ull;

        __syncthreads();

        // software-pipelined: prefetch next j-pair while computing current
        ulonglong2 v = s_cxy[0];
        u64 nb2 = s_nb2[0];
        #pragma unroll 8
        for (int p = 0; p < JPAIRS; p++) {
            ulonglong2 vn = s_cxy[p + 1];
            u64 nbn = s_nb2[p + 1];
            // nd = 2*xi.xj - (1 + hi + hj) = -(1 + d2)
            u64 s0 = add2(nb2, nha);
            u64 s1 = add2(nb2, nhb);
            s0 = fma2(v.y, xay2, s0);
            s1 = fma2(v.y, xby2, s1);
            u64 nd0 = fma2(v.x, xax2, s0);
            u64 nd1 = fma2(v.x, xbx2, s1);
            u64 y00 = MAGIC2 - nd0;              // packed magic rcp seed
            u64 y01 = MAGIC2 - nd1;
            u64 t0 = fma2(nd0, y00, TWO2);       // Newton
            u64 t1 = fma2(nd1, y01, TWO2);
            acc0 = fma2(y00, t0, acc0);
            acc1 = fma2(y01, t1, acc1);
            v = vn; nb2 = nbn;
        }

        float a0l, a0h, a1l, a1h;
        unpack2f(a0l, a0h, acc0);
        unpack2f(a1l, a1h, acc1);
        float sres = block_reduce((a0l + a0h) + (a1l + a1h), sred);
        if (tid == 0) g_part_p[bid] = sres * wt;
    } else {
        // -------- pairs path + KLD slice -----------------------------------------
        int pb = bid - HEAVY_BLOCKS;
        float term = 0.0f, psum = 0.0f;
        int base = pb * 1024;
        #pragma unroll
        for (int r = 0; r < 4; r++) {
            int p = base + r * 256 + tid;
            int ai = ii[p], bi = jj[p];
            float2 ma = ((const float2*)mu)[ai];
            float2 la = ((const float2*)lv)[ai];
            float2 ea = ((const float2*)epsi)[p];
            float2 mb = ((const float2*)mu)[bi];
            float2 lb = ((const float2*)lv)[bi];
            float2 eb = ((const float2*)epsj)[p];
            float xax = fmaf(ea.x, __expf(0.5f * la.x), ma.x);
            float xay = fmaf(ea.y, __expf(0.5f * la.y), ma.y);
            float xbx = fmaf(eb.x, __expf(0.5f * lb.x), mb.x);
            float xby = fmaf(eb.y, __expf(0.5f * lb.y), mb.y);
            float da = xax - xbx, db = xay - xby;
            float d2 = fmaf(da, da, db * db);
            float pv = pij[p];
            // pij*(log pij - log qij) = pij*(log pij + log(1+d2)) + pij*log(part)
            term += pv * (logf(pv) + log1pf(d2));
            psum += pv;
        }
        // KLD slice: 256 points per pair-block (64 * 256 = 16384)
        float kld;
        {
            int idx = pb * 256 + tid;
            float2 m = ((const float2*)mu)[idx];
            float2 l = ((const float2*)lv)[idx];
            kld = (1.0f + l.x - m.x * m.x - __expf(l.x))
                + (1.0f + l.y - m.y * m.y - __expf(l.y));
        }
        float s0 = block_reduce(term, sred);
        __syncthreads();
        float s1 = block_reduce(psum, sred1);
        __syncthreads();
        float s2 = block_reduce(kld, sred);
        if (tid == 0) {
            g_pair_p[pb] = s0;
            g_pij_p[pb]  = s1;
            g_kld_p[pb]  = s2;
        }
    }

    // -------- fused final: last CTA reduces everything ----------------------------
    __threadfence();
    if (tid == 0) s_last = atomicAdd(&g_ticket, 1u);
    __syncthreads();
    if (s_last == NBLOCKS - 1) {
        __threadfence();
        double part = 0.0, kld = 0.0, pair = 0.0, pijs = 0.0;
        for (int t = tid; t < HEAVY_BLOCKS; t += 256) part += (double)g_part_p[t];
        if (tid < PAIR_BLOCKS) {
            kld  = (double)g_kld_p[tid];
            pair = (double)g_pair_p[tid];
            pijs = (double)g_pij_p[tid];
        }
        double vals[4] = {part, kld, pair, pijs};
        double res[4];
        #pragma unroll
        for (int k = 0; k < 4; k++) {
            sdd[tid] = vals[k];
            __syncthreads();
            for (int o = 128; o > 0; o >>= 1) {
                if (tid < o) sdd[tid] += sdd[tid + o];
                __syncthreads();
            }
            res[k] = sdd[0];
            __syncthreads();
        }
        if (tid == 0) {
            double partv = res[0] - (double)N_POINTS;   // remove diagonal
            double loss = res[2] + res[3] * log(partv) + 1e-7 * (-0.5 * res[1]);
            out[0] = (float)loss;
            g_ticket = 0;   // reset for next graph replay
        }
    }
}

// -----------------------------------------------------------------------------
extern "C" void kernel_launch(void* const* d_in, const int* in_sizes, int n_in,
                              void* d_out, int out_size) {
    const float* pij      = (const float*)d_in[0];
    const int*   i_idx    = (const int*)  d_in[1];
    const int*   j_idx    = (const int*)  d_in[2];
    const float* mu_w     = (const float*)d_in[3];
    const float* lv_w     = (const float*)d_in[4];
    const float* eps_full = (const float*)d_in[5];
    const float* eps_i    = (const float*)d_in[6];
    const float* eps_j    = (const float*)d_in[7];
    float* out = (float*)d_out;

    k_main<<<NBLOCKS, 256>>>(pij, i_idx, j_idx, mu_w, lv_w,
                             eps_full, eps_i, eps_j, out);
}

// round 7
// speedup vs baseline: 2.6076x; 1.0608x over previous
#include <cuda_runtime.h>
#include <math.h>

#define N_POINTS 16384
#define N_PAIRS  65536

#define T_GRID   32                      // 32x32 tiles of 512 points
#define HEAVY_BLOCKS 528                 // T*(T+1)/2 upper-triangle tiles (512x512)
#define PAIR_BLOCKS  64
#define NBLOCKS  (HEAVY_BLOCKS + PAIR_BLOCKS)    // 592 = 4 * 148 exactly
#define JTILE 512
#define JPAIRS (JTILE / 2)               // 256 packed j-pairs
#define JSTEPS (JPAIRS / 4)              // 64 steps, 4 pairs (8 j's) per step

typedef unsigned long long u64;
typedef unsigned int u32;

// ---- device scratch (no allocation allowed) ----------------------------------
__device__ float g_part_p[HEAVY_BLOCKS];
__device__ float g_kld_p[PAIR_BLOCKS];
__device__ float g_pair_p[PAIR_BLOCKS];
__device__ float g_pij_p[PAIR_BLOCKS];
__device__ unsigned int g_ticket = 0;

// ---- packed f32x2 helpers -----------------------------------------------------
__device__ __forceinline__ u64 pack2(float lo, float hi) {
    u64 r; asm("mov.b64 %0, {%1, %2};" : "=l"(r) : "f"(lo), "f"(hi)); return r;
}
__device__ __forceinline__ void unpack2f(float& lo, float& hi, u64 v) {
    asm("mov.b64 {%0, %1}, %2;" : "=f"(lo), "=f"(hi) : "l"(v));
}
__device__ __forceinline__ u64 fma2(u64 a, u64 b, u64 c) {
    u64 d; asm("fma.rn.f32x2 %0, %1, %2, %3;" : "=l"(d) : "l"(a), "l"(b), "l"(c)); return d;
}
__device__ __forceinline__ u64 add2(u64 a, u64 b) {
    u64 d; asm("add.rn.f32x2 %0, %1, %2;" : "=l"(d) : "l"(a), "l"(b)); return d;
}
__device__ __forceinline__ u64 mul2(u64 a, u64 b) {
    u64 d; asm("mul.rn.f32x2 %0, %1, %2;" : "=l"(d) : "l"(a), "l"(b)); return d;
}

// ---- reductions ----------------------------------------------------------------
__device__ __forceinline__ float warp_reduce(float v) {
    #pragma unroll
    for (int o = 16; o > 0; o >>= 1) v += __shfl_xor_sync(0xffffffffu, v, o);
    return v;
}
__device__ __forceinline__ float block_reduce(float v, float* smem) {
    v = warp_reduce(v);
    int lane = threadIdx.x & 31, wid = threadIdx.x >> 5;
    if (lane == 0) smem[wid] = v;
    __syncthreads();
    v = (threadIdx.x < 8) ? smem[threadIdx.x] : 0.0f;
    if (wid == 0) {
        #pragma unroll
        for (int o = 4; o > 0; o >>= 1) v += __shfl_xor_sync(0xffffffffu, v, o);
    }
    return v;  // valid in thread 0
}

// ---- reparam helper: x = eps*exp(0.5*lv) + mu ----------------------------------
__device__ __forceinline__ float2 reparam_pt(const float* __restrict__ mu,
                                             const float* __restrict__ lv,
                                             const float* __restrict__ eps,
                                             int idx) {
    float2 m = ((const float2*)mu)[idx];
    float2 l = ((const float2*)lv)[idx];
    float2 e = ((const float2*)eps)[idx];
    float2 x;
    x.x = fmaf(e.x, __expf(0.5f * l.x), m.x);
    x.y = fmaf(e.y, __expf(0.5f * l.y), m.y);
    return x;
}

// batch-4-unit reciprocal sum for one i-chain; accumulates -(sum of 8 recips)
// cx = -2*xjx, cy = -2*xjy, b = 1 + |xj|^2, hi2 = |xi|^2 (NO +1 here!)
// d = (1 + hj + hi) - 2*xi.xj = 1 + dist^2 >= 1
__device__ __forceinline__ void batch8(u64 cx01, u64 cx23, u64 cx45, u64 cx67,
                                       u64 cy01, u64 cy23, u64 cy45, u64 cy67,
                                       u64 b01,  u64 b23,  u64 b45,  u64 b67,
                                       u64 xix2, u64 xiy2, u64 hi2,
                                       u64 TWO2, u64& acc) {
    const u64 MAGIC2 = 0xFEF127EAFEF127EAull;
    u64 d0 = fma2(cx01, xix2, fma2(cy01, xiy2, add2(b01, hi2)));
    u64 d1 = fma2(cx23, xix2, fma2(cy23, xiy2, add2(b23, hi2)));
    u64 d2 = fma2(cx45, xix2, fma2(cy45, xiy2, add2(b45, hi2)));
    u64 d3 = fma2(cx67, xix2, fma2(cy67, xiy2, add2(b67, hi2)));
    // 1/d0+1/d1+1/d2+1/d3 = (S01*P23 + S23*P01) / (P01*P23), per packed lane
    u64 P01 = mul2(d0, d1), S01 = add2(d0, d1);
    u64 P23 = mul2(d2, d3), S23 = add2(d2, d3);
    u64 N = fma2(S23, P01, mul2(S01, P23));
    u64 D = mul2(P01, P23);
    u64 ny0 = MAGIC2 - D;              // ~ -1/D (sign bit lands set; no borrow)
    u64 t = fma2(D, ny0, TWO2);        // 2 - D*y0
    u64 q = mul2(N, ny0);              // -N*y0
    acc = fma2(q, t, acc);             // acc += -(N/D)*(1 - e^2)
}

// ---- single fused kernel --------------------------------------------------------
__global__ __launch_bounds__(256, 4)
void k_main(const float* __restrict__ pij,
            const int*   __restrict__ ii,
            const int*   __restrict__ jj,
            const float* __restrict__ mu,
            const float* __restrict__ lv,
            const float* __restrict__ epsf,
            const float* __restrict__ epsi,
            const float* __restrict__ epsj,
            float* __restrict__ out) {
    __shared__ __align__(16) u64 s_cx[JPAIRS];  // per j-pair: (-2x)_lane01
    __shared__ __align__(16) u64 s_cy[JPAIRS];
    __shared__ __align__(16) u64 s_b [JPAIRS];  // per j-pair: 1+|xj|^2
    __shared__ float  sred[8];
    __shared__ float  sred1[8];
    __shared__ double sdd[256];
    __shared__ unsigned int s_last;

    const int bid = blockIdx.x;
    const int tid = threadIdx.x;

    if (bid < HEAVY_BLOCKS) {
        // -------- heavy path: upper-tri tile (a,b) at 512 granularity -----------
        int a = 0, rem = bid;
        while (rem >= T_GRID - a) { rem -= T_GRID - a; a++; }
        int b = a + rem;
        int i0 = a * 512;
        int j0 = b * 512;
        float wt = (a == b) ? 1.0f : 2.0f;

        // build j-tile in shared (reparam on the fly): 512 j's
        #pragma unroll
        for (int r = 0; r < 2; r++) {
            int jg = j0 + r * 256 + tid;
            float2 xj = reparam_pt(mu, lv, epsf, jg);
            float cx = -2.0f * xj.x, cy = -2.0f * xj.y;
            float bb = fmaf(xj.x, xj.x, fmaf(xj.y, xj.y, 1.0f));
            float cxn = __shfl_down_sync(0xffffffffu, cx, 1);
            float cyn = __shfl_down_sync(0xffffffffu, cy, 1);
            float bbn = __shfl_down_sync(0xffffffffu, bb, 1);
            if ((tid & 1) == 0) {
                int p = (r * 256 + tid) >> 1;
                s_cx[p] = pack2(cx, cxn);
                s_cy[p] = pack2(cy, cyn);
                s_b [p] = pack2(bb, bbn);
            }
        }

        // two i-chains per thread (512 i per CTA)
        float2 xa = reparam_pt(mu, lv, epsf, i0 + tid);
        float2 xb = reparam_pt(mu, lv, epsf, i0 + 256 + tid);
        u64 xax2 = pack2(xa.x, xa.x), xay2 = pack2(xa.y, xa.y);
        u64 xbx2 = pack2(xb.x, xb.x), xby2 = pack2(xb.y, xb.y);
        float haf = fmaf(xa.x, xa.x, xa.y * xa.y);   // |xi|^2, no +1
        float hbf = fmaf(xb.x, xb.x, xb.y * xb.y);
        u64 ha2 = pack2(haf, haf);
        u64 hb2 = pack2(hbf, hbf);
        const u64 TWO2 = pack2(2.0f, 2.0f);
        u64 acc0 = 0ull, acc1 = 0ull;

        __syncthreads();

        #pragma unroll 4
        for (int st = 0; st < JSTEPS; st++) {
            int p4 = st * 4;
            ulonglong2 cxA = *(const ulonglong2*)&s_cx[p4];
            ulonglong2 cxB = *(const ulonglong2*)&s_cx[p4 + 2];
            ulonglong2 cyA = *(const ulonglong2*)&s_cy[p4];
            ulonglong2 cyB = *(const ulonglong2*)&s_cy[p4 + 2];
            ulonglong2 bA  = *(const ulonglong2*)&s_b [p4];
            ulonglong2 bB  = *(const ulonglong2*)&s_b [p4 + 2];
            batch8(cxA.x, cxA.y, cxB.x, cxB.y,
                   cyA.x, cyA.y, cyB.x, cyB.y,
                   bA.x,  bA.y,  bB.x,  bB.y,
                   xax2, xay2, ha2, TWO2, acc0);
            batch8(cxA.x, cxA.y, cxB.x, cxB.y,
                   cyA.x, cyA.y, cyB.x, cyB.y,
                   bA.x,  bA.y,  bB.x,  bB.y,
                   xbx2, xby2, hb2, TWO2, acc1);
        }

        float a0l, a0h, a1l, a1h;
        unpack2f(a0l, a0h, acc0);
        unpack2f(a1l, a1h, acc1);
        // acc holds negated sums
        float sres = block_reduce(-((a0l + a0h) + (a1l + a1h)), sred);
        if (tid == 0) g_part_p[bid] = sres * wt;
    } else {
        // -------- pairs path + KLD slice -----------------------------------------
        int pb = bid - HEAVY_BLOCKS;
        float term = 0.0f, psum = 0.0f;
        int base = pb * 1024;
        #pragma unroll
        for (int r = 0; r < 4; r++) {
            int p = base + r * 256 + tid;
            int ai = ii[p], bi = jj[p];
            float2 ma = ((const float2*)mu)[ai];
            float2 la = ((const float2*)lv)[ai];
            float2 ea = ((const float2*)epsi)[p];
            float2 mb = ((const float2*)mu)[bi];
            float2 lb = ((const float2*)lv)[bi];
            float2 eb = ((const float2*)epsj)[p];
            float xax = fmaf(ea.x, __expf(0.5f * la.x), ma.x);
            float xay = fmaf(ea.y, __expf(0.5f * la.y), ma.y);
            float xbx = fmaf(eb.x, __expf(0.5f * lb.x), mb.x);
            float xby = fmaf(eb.y, __expf(0.5f * lb.y), mb.y);
            float da = xax - xbx, db = xay - xby;
            float d2 = fmaf(da, da, db * db);
            float pv = pij[p];
            // pij*(log pij - log qij) = pij*(log pij + log(1+d2)) + pij*log(part)
            term += pv * (logf(pv) + log1pf(d2));
            psum += pv;
        }
        // KLD slice: 256 points per pair-block (64 * 256 = 16384)
        float kld;
        {
            int idx = pb * 256 + tid;
            float2 m = ((const float2*)mu)[idx];
            float2 l = ((const float2*)lv)[idx];
            kld = (1.0f + l.x - m.x * m.x - __expf(l.x))
                + (1.0f + l.y - m.y * m.y - __expf(l.y));
        }
        float s0 = block_reduce(term, sred);
        __syncthreads();
        float s1 = block_reduce(psum, sred1);
        __syncthreads();
        float s2 = block_reduce(kld, sred);
        if (tid == 0) {
            g_pair_p[pb] = s0;
            g_pij_p[pb]  = s1;
            g_kld_p[pb]  = s2;
        }
    }

    // -------- fused final: last CTA reduces everything ----------------------------
    __threadfence();
    if (tid == 0) s_last = atomicAdd(&g_ticket, 1u);
    __syncthreads();
    if (s_last == NBLOCKS - 1) {
        __threadfence();
        double part = 0.0, kld = 0.0, pair = 0.0, pijs = 0.0;
        for (int t = tid; t < HEAVY_BLOCKS; t += 256) part += (double)g_part_p[t];
        if (tid < PAIR_BLOCKS) {
            kld  = (double)g_kld_p[tid];
            pair = (double)g_pair_p[tid];
            pijs = (double)g_pij_p[tid];
        }
        double vals[4] = {part, kld, pair, pijs};
        double res[4];
        #pragma unroll
        for (int k = 0; k < 4; k++) {
            sdd[tid] = vals[k];
            __syncthreads();
            for (int o = 128; o > 0; o >>= 1) {
                if (tid < o) sdd[tid] += sdd[tid + o];
                __syncthreads();
            }
            res[k] = sdd[0];
            __syncthreads();
        }
        if (tid == 0) {
            double partv = res[0] - (double)N_POINTS;   // remove diagonal
            double loss = res[2] + res[3] * log(partv) + 1e-7 * (-0.5 * res[1]);
            out[0] = (float)loss;
            g_ticket = 0;   // reset for next graph replay
        }
    }
}

// -----------------------------------------------------------------------------
extern "C" void kernel_launch(void* const* d_in, const int* in_sizes, int n_in,
                              void* d_out, int out_size) {
    const float* pij      = (const float*)d_in[0];
    const int*   i_idx    = (const int*)  d_in[1];
    const int*   j_idx    = (const int*)  d_in[2];
    const float* mu_w     = (const float*)d_in[3];
    const float* lv_w     = (const float*)d_in[4];
    const float* eps_full = (const float*)d_in[5];
    const float* eps_i    = (const float*)d_in[6];
    const float* eps_j    = (const float*)d_in[7];
    float* out = (float*)d_out;

    k_main<<<NBLOCKS, 256>>>(pij, i_idx, j_idx, mu_w, lv_w,
                             eps_full, eps_i, eps_j, out);
}